// round 4
// baseline (speedup 1.0000x reference)
#include <cuda_runtime.h>
#include <math.h>

#define C 512
#define HWN 1024
#define CHW (C*HWN)

__device__ __align__(16) float d_G[1024];        // G[i*32+x]
__device__ float d_mean[C];
__device__ float d_scale[C];
__device__ __align__(16) float d_out32[CHW];     // [c][hw]
__device__ __align__(16) float d_out32T[CHW];    // [hw][c]
__device__ __align__(16) float d_sigT[CHW];      // [hw][c]
__device__ __align__(16) float d_cat[2*CHW];     // gus flat (p*512+c) ; csa flat
__device__ __align__(16) float d_y[CHW];

#define FMA2(acc, a, b) asm("fma.rn.f32x2 %0, %1, %2, %0;" : "+l"(acc) : "l"(a), "l"(b))

// ---- blocks 0..511: channel means; block 512: gaussian weights ----
__global__ void k_init(const float* __restrict__ x) {
    if (blockIdx.x == 512) {
        int i = threadIdx.x;
        if (i < 32) {
            float ev[32]; float s = 0.f;
            #pragma unroll
            for (int xx = 0; xx < 32; xx++) {
                float dd = (float)(xx - i);
                float e = expf(-dd * dd * (1.0f/4.5f));
                ev[xx] = e; s += e;
            }
            float inv = 1.f / s;
            #pragma unroll
            for (int xx = 0; xx < 32; xx++) d_G[i*32 + xx] = ev[xx] * inv;
        }
        return;
    }
    int c = blockIdx.x, t = threadIdx.x;
    float4 v = reinterpret_cast<const float4*>(x + c*HWN)[t];
    float s = v.x + v.y + v.z + v.w;
    #pragma unroll
    for (int o = 16; o > 0; o >>= 1) s += __shfl_xor_sync(~0u, s, o);
    __shared__ float red[8];
    if ((t & 31) == 0) red[t >> 5] = s;
    __syncthreads();
    if (t == 0) {
        float tot = 0.f;
        #pragma unroll
        for (int w = 0; w < 8; w++) tot += red[w];
        d_mean[c] = tot * (1.f/1024.f);
    }
}

// ---- SE: fc -> relu -> fc -> sigmoid ----
__global__ void k_se(const float* __restrict__ w1, const float* __restrict__ w2) {
    __shared__ float s[512], s1[32];
    int t = threadIdx.x;
    s[t] = d_mean[t];
    __syncthreads();
    int o = t >> 4, l = t & 15;
    float a = 0.f;
    #pragma unroll
    for (int j = 0; j < 8; j++) {
        int c = (l + j*16) * 4;
        float4 w = *reinterpret_cast<const float4*>(w1 + o*512 + c);
        a += w.x*s[c] + w.y*s[c+1] + w.z*s[c+2] + w.w*s[c+3];
    }
    #pragma unroll
    for (int off = 8; off > 0; off >>= 1) a += __shfl_down_sync(~0u, a, off, 16);
    if (l == 0) s1[o] = fmaxf(a, 0.f);
    __syncthreads();
    float b = 0.f;
    const float4* w2p = reinterpret_cast<const float4*>(w2 + t*32);
    #pragma unroll
    for (int j = 0; j < 8; j++) {
        float4 w = w2p[j];
        b += w.x*s1[j*4+0] + w.y*s1[j*4+1] + w.z*s1[j*4+2] + w.w*s1[j*4+3];
    }
    d_scale[t] = 1.f / (1.f + expf(-b));
}

// ---- scale + sigmoid + transpose (64ch x 32px tiles) ----
__global__ void k_trans(const float* __restrict__ x) {
    int p0 = blockIdx.x * 32;
    int c0 = blockIdx.y * 64;
    int t = threadIdx.x;
    __shared__ float V[64][33], S[64][33];
    int r = t >> 3, q = (t & 7) * 4;
    #pragma unroll
    for (int hh = 0; hh < 2; hh++) {
        int rr = r + hh*32;
        float4 xv = *reinterpret_cast<const float4*>(x + (c0 + rr)*HWN + p0 + q);
        float sc = d_scale[c0 + rr];
        float4 v; v.x = xv.x*sc; v.y = xv.y*sc; v.z = xv.z*sc; v.w = xv.w*sc;
        *reinterpret_cast<float4*>(d_out32 + (c0 + rr)*HWN + p0 + q) = v;
        V[rr][q+0] = v.x; V[rr][q+1] = v.y; V[rr][q+2] = v.z; V[rr][q+3] = v.w;
        S[rr][q+0] = 1.f/(1.f+expf(-v.x));
        S[rr][q+1] = 1.f/(1.f+expf(-v.y));
        S[rr][q+2] = 1.f/(1.f+expf(-v.z));
        S[rr][q+3] = 1.f/(1.f+expf(-v.w));
    }
    __syncthreads();
    int pr = t >> 3;
    #pragma unroll
    for (int hh = 0; hh < 2; hh++) {
        int cc = (t & 7) * 4 + hh*32;
        float4 ov, sv;
        ov.x = V[cc+0][pr]; ov.y = V[cc+1][pr]; ov.z = V[cc+2][pr]; ov.w = V[cc+3][pr];
        sv.x = S[cc+0][pr]; sv.y = S[cc+1][pr]; sv.z = S[cc+2][pr]; sv.w = S[cc+3][pr];
        *reinterpret_cast<float4*>(d_out32T + (p0 + pr)*512 + c0 + cc) = ov;
        *reinterpret_cast<float4*>(d_sigT   + (p0 + pr)*512 + c0 + cc) = sv;
    }
}

// ---- fused: blocks 0..127 = full separable gaussian (4 ch each);
//      blocks 128..1151 = CSA per pixel ----
__global__ void k_fuse3() {
    __shared__ float sm[10240];   // 40KB
    int t = threadIdx.x;
    if (blockIdx.x < 128) {
        int c0 = blockIdx.x * 4;
        float* sG  = sm;            // [1024] G[i*32+x]
        float* sGT = sm + 1024;     // [1024] GT[y*32+k] = G[k*32+y]
        float* sO  = sm + 2048;     // [4][1024]
        float* sT  = sm + 6144;     // [4][1024]
        #pragma unroll
        for (int j = 0; j < 4; j++) {
            int l = t + j*256;
            sG[l] = d_G[l];
            sGT[l] = d_G[(l & 31)*32 + (l >> 5)];
        }
        #pragma unroll
        for (int j = 0; j < 4; j++) {
            int idx = t + j*256;   // float4 index over 4096 floats
            reinterpret_cast<float4*>(sO)[idx] =
                *reinterpret_cast<const float4*>(d_out32 + (size_t)c0*1024 + idx*4);
        }
        __syncthreads();
        // stage 1: sT[ch][i*32+y] = sum_x G[i,x]*sO[ch][x*32+y]
        int ch = t >> 6, lane64 = t & 63;
        #pragma unroll
        for (int j = 0; j < 16; j++) {
            int e = lane64 + j*64;
            int i = e >> 5, y = e & 31;
            float acc = 0.f;
            #pragma unroll
            for (int xx = 0; xx < 32; xx++)
                acc += sG[i*32 + xx] * sO[ch*1024 + xx*32 + y];
            sT[ch*1024 + e] = acc;
        }
        __syncthreads();
        // stage 2: cat[p*512 + c0 + ch] = sum_y G[k,y]*sT[ch][i*32+y]
        #pragma unroll
        for (int j = 0; j < 4; j++) {
            int p = t + j*256;
            int i = p >> 5, k = p & 31;
            float4 o = make_float4(0.f, 0.f, 0.f, 0.f);
            #pragma unroll
            for (int y = 0; y < 32; y++) {
                float g = sGT[y*32 + k];
                o.x += g * sT[0*1024 + i*32 + y];
                o.y += g * sT[1*1024 + i*32 + y];
                o.z += g * sT[2*1024 + i*32 + y];
                o.w += g * sT[3*1024 + i*32 + y];
            }
            *reinterpret_cast<float4*>(d_cat + (size_t)p*512 + c0) = o;
        }
    } else {
        int p = blockIdx.x - 128;
        int h = p >> 5, w = p & 31;
        float* wred = sm;        // [8][9]
        float* sA = sm + 72;     // [9]
        int pn[9]; bool val[9];
        #pragma unroll
        for (int di = 0; di < 3; di++)
            #pragma unroll
            for (int dj = 0; dj < 3; dj++) {
                int d = di*3 + dj;
                int gh = h + di - 1, gw = w + dj - 1;
                val[d] = (gh >= 0) & (gh < 32) & (gw >= 0) & (gw < 32);
                pn[d] = (gh*32 + gw) * 512;
            }
        float2 cen = *reinterpret_cast<const float2*>(d_sigT + p*512 + t*2);
        float part[9];
        #pragma unroll
        for (int d = 0; d < 9; d++) {
            float pd = 0.f;
            if (val[d]) {
                float2 nb = *reinterpret_cast<const float2*>(d_sigT + pn[d] + t*2);
                pd = cen.x*nb.x + cen.y*nb.y;
            }
            part[d] = pd;
        }
        int lane = t & 31, wid = t >> 5;
        #pragma unroll
        for (int d = 0; d < 9; d++) {
            float v = part[d];
            #pragma unroll
            for (int o = 16; o > 0; o >>= 1) v += __shfl_xor_sync(~0u, v, o);
            if (lane == 0) wred[wid*9 + d] = v;
        }
        __syncthreads();
        if (t == 0) {
            float sc[9];
            #pragma unroll
            for (int d = 0; d < 9; d++) {
                float s = 0.f;
                #pragma unroll
                for (int q = 0; q < 8; q++) s += wred[q*9 + d];
                sc[d] = s * (1.f/512.f);
            }
            float m = sc[0];
            #pragma unroll
            for (int d = 1; d < 9; d++) m = fmaxf(m, sc[d]);
            float e[9], ss = 0.f;
            #pragma unroll
            for (int d = 0; d < 9; d++) { e[d] = expf(sc[d] - m); ss += e[d]; }
            float inv = 1.f / ss;
            #pragma unroll
            for (int d = 0; d < 9; d++) sA[d] = e[d] * inv;
        }
        __syncthreads();
        float2 acc = make_float2(0.f, 0.f);
        #pragma unroll
        for (int d = 0; d < 9; d++) {
            if (val[d]) {
                float a = sA[d];
                float2 nb = *reinterpret_cast<const float2*>(d_out32T + pn[d] + t*2);
                acc.x += a*nb.x; acc.y += a*nb.y;
            }
        }
        *reinterpret_cast<float2*>(d_cat + CHW + p*512 + t*2) = acc;
    }
}

// ---- GEMM (f32x2, dup-A smem, zero-mov inner loop) ----
__global__ void k_gemm(const float* __restrict__ Wd) {
    int n0 = blockIdx.x * 64;
    int m0 = blockIdx.y * 64;
    int t = threadIdx.x;
    __shared__ float2 As2[16][64];   // duplicated A values
    __shared__ float  Bs[16][64];
    int tx = t & 15, ty = t >> 4;
    int ao = t >> 2,  akq = (t & 3) * 4;
    int bk = t >> 4,  bnq = (t & 15) * 4;
    const float* aptr = Wd + (m0 + ao)*1024 + akq;
    const float* bptr = d_cat + (size_t)bk*1024 + n0 + bnq;
    float4 aR = *reinterpret_cast<const float4*>(aptr);
    float4 bR = *reinterpret_cast<const float4*>(bptr);
    unsigned long long acc[4][2];
    #pragma unroll
    for (int u = 0; u < 4; u++) { acc[u][0] = 0ull; acc[u][1] = 0ull; }
    for (int k0 = 0; k0 < 1024; k0 += 16) {
        As2[akq+0][ao] = make_float2(aR.x, aR.x);
        As2[akq+1][ao] = make_float2(aR.y, aR.y);
        As2[akq+2][ao] = make_float2(aR.z, aR.z);
        As2[akq+3][ao] = make_float2(aR.w, aR.w);
        *reinterpret_cast<float4*>(&Bs[bk][bnq]) = bR;
        __syncthreads();
        if (k0 + 16 < 1024) {
            aR = *reinterpret_cast<const float4*>(aptr + k0 + 16);
            bR = *reinterpret_cast<const float4*>(bptr + (size_t)(k0 + 16)*1024);
        }
        #pragma unroll
        for (int kk = 0; kk < 16; kk++) {
            ulonglong2 b2  = *reinterpret_cast<const ulonglong2*>(&Bs[kk][tx*4]);
            ulonglong2 a01 = *reinterpret_cast<const ulonglong2*>(&As2[kk][ty*4]);
            ulonglong2 a23 = *reinterpret_cast<const ulonglong2*>(&As2[kk][ty*4+2]);
            FMA2(acc[0][0], a01.x, b2.x); FMA2(acc[0][1], a01.x, b2.y);
            FMA2(acc[1][0], a01.y, b2.x); FMA2(acc[1][1], a01.y, b2.y);
            FMA2(acc[2][0], a23.x, b2.x); FMA2(acc[2][1], a23.x, b2.y);
            FMA2(acc[3][0], a23.y, b2.x); FMA2(acc[3][1], a23.y, b2.y);
        }
        __syncthreads();
    }
    #pragma unroll
    for (int u = 0; u < 4; u++) {
        float4 o4;
        asm("mov.b64 {%0,%1}, %2;" : "=f"(o4.x), "=f"(o4.y) : "l"(acc[u][0]));
        asm("mov.b64 {%0,%1}, %2;" : "=f"(o4.z), "=f"(o4.w) : "l"(acc[u][1]));
        *reinterpret_cast<float4*>(d_y + (m0 + ty*4 + u)*1024 + n0 + tx*4) = o4;
    }
}

// ---- instance norm + leaky relu(0.2) ----
__global__ void k_inorm(float* __restrict__ out) {
    int o = blockIdx.x, t = threadIdx.x;
    __shared__ float red[8];
    __shared__ float bmu, brs;
    float4 v = reinterpret_cast<const float4*>(d_y + o*1024)[t];
    float s = v.x + v.y + v.z + v.w;
    #pragma unroll
    for (int off = 16; off > 0; off >>= 1) s += __shfl_xor_sync(~0u, s, off);
    if ((t & 31) == 0) red[t >> 5] = s;
    __syncthreads();
    if (t == 0) {
        float tot = 0.f;
        #pragma unroll
        for (int w = 0; w < 8; w++) tot += red[w];
        bmu = tot * (1.f/1024.f);
    }
    __syncthreads();
    float mu = bmu;
    float dx = v.x - mu, dy = v.y - mu, dz = v.z - mu, dw = v.w - mu;
    float q = dx*dx + dy*dy + dz*dz + dw*dw;
    #pragma unroll
    for (int off = 16; off > 0; off >>= 1) q += __shfl_xor_sync(~0u, q, off);
    if ((t & 31) == 0) red[t >> 5] = q;
    __syncthreads();
    if (t == 0) {
        float tot = 0.f;
        #pragma unroll
        for (int w = 0; w < 8; w++) tot += red[w];
        brs = rsqrtf(tot * (1.f/1024.f) + 1e-5f);
    }
    __syncthreads();
    float rs = brs;
    float4 r;
    r.x = dx*rs; r.y = dy*rs; r.z = dz*rs; r.w = dw*rs;
    r.x = r.x >= 0.f ? r.x : 0.2f*r.x;
    r.y = r.y >= 0.f ? r.y : 0.2f*r.y;
    r.z = r.z >= 0.f ? r.z : 0.2f*r.z;
    r.w = r.w >= 0.f ? r.w : 0.2f*r.w;
    reinterpret_cast<float4*>(out + o*1024)[t] = r;
}

extern "C" void kernel_launch(void* const* d_in, const int* in_sizes, int n_in,
                              void* d_out, int out_size) {
    const float* x  = (const float*)d_in[0];
    const float* w1 = (const float*)d_in[1];
    const float* w2 = (const float*)d_in[2];
    const float* wd = (const float*)d_in[3];
    float* out = (float*)d_out;

    k_init<<<513, 256>>>(x);
    k_se<<<1, 512>>>(w1, w2);
    k_trans<<<dim3(32, 8), 256>>>(x);
    k_fuse3<<<1152, 256>>>();
    k_gemm<<<dim3(16, 8), 256>>>(wd);
    k_inorm<<<512, 256>>>(out);
}

// round 6
// speedup vs baseline: 2.2965x; 2.2965x over previous
#include <cuda_runtime.h>
#include <cuda_bf16.h>
#include <math.h>
#include <stdint.h>

#define C 512
#define HWN 1024
#define CHW (C*HWN)

__device__ __align__(16) float d_G[1024];        // G[i*32+x]
__device__ float d_mean[C];
__device__ float d_scale[C];
__device__ __align__(16) float d_out32[CHW];     // [c][hw]
__device__ __align__(16) float d_out32T[CHW];    // [hw][c]
__device__ __align__(16) float d_sigT[CHW];      // [hw][c]
__device__ __align__(16) float d_tmp[CHW];       // [c][i*32+y]
__device__ __align__(16) float d_cat[2*CHW];     // gus flat (p*512+c) ; csa flat
__device__ __align__(16) float d_y[4*CHW];       // 4 k-split partials

// ---- Gaussian weights ----
__global__ void k_gauss() {
    int i = threadIdx.x; // 0..31
    float ev[32]; float s = 0.f;
    #pragma unroll
    for (int x = 0; x < 32; x++) {
        float dd = (float)(x - i);
        float e = expf(-dd * dd * (1.0f/4.5f));
        ev[x] = e; s += e;
    }
    float inv = 1.f / s;
    #pragma unroll
    for (int x = 0; x < 32; x++) d_G[i*32 + x] = ev[x] * inv;
}

// ---- channel means ----
__global__ void k_mean(const float* __restrict__ x) {
    int c = blockIdx.x, t = threadIdx.x;
    float4 v = reinterpret_cast<const float4*>(x + c*HWN)[t];
    float s = v.x + v.y + v.z + v.w;
    #pragma unroll
    for (int o = 16; o > 0; o >>= 1) s += __shfl_xor_sync(~0u, s, o);
    __shared__ float red[8];
    if ((t & 31) == 0) red[t >> 5] = s;
    __syncthreads();
    if (t == 0) {
        float tot = 0.f;
        #pragma unroll
        for (int w = 0; w < 8; w++) tot += red[w];
        d_mean[c] = tot * (1.f/1024.f);
    }
}

// ---- SE ----
__global__ void k_se(const float* __restrict__ w1, const float* __restrict__ w2) {
    __shared__ float s[512], s1[32];
    int t = threadIdx.x;
    s[t] = d_mean[t];
    __syncthreads();
    int o = t >> 4, l = t & 15;
    float a = 0.f;
    #pragma unroll
    for (int j = 0; j < 8; j++) {
        int c = (l + j*16) * 4;
        float4 w = *reinterpret_cast<const float4*>(w1 + o*512 + c);
        a += w.x*s[c] + w.y*s[c+1] + w.z*s[c+2] + w.w*s[c+3];
    }
    #pragma unroll
    for (int off = 8; off > 0; off >>= 1) a += __shfl_down_sync(~0u, a, off, 16);
    if (l == 0) s1[o] = fmaxf(a, 0.f);
    __syncthreads();
    float b = 0.f;
    const float4* w2p = reinterpret_cast<const float4*>(w2 + t*32);
    #pragma unroll
    for (int j = 0; j < 8; j++) {
        float4 w = w2p[j];
        b += w.x*s1[j*4+0] + w.y*s1[j*4+1] + w.z*s1[j*4+2] + w.w*s1[j*4+3];
    }
    d_scale[t] = 1.f / (1.f + expf(-b));
}

// ---- scale + sigmoid + transpose ----
__global__ void k_trans(const float* __restrict__ x) {
    int p0 = blockIdx.x * 32;
    int c0 = blockIdx.y * 32;
    int t = threadIdx.x;
    __shared__ float V[32][33], S[32][33];
    int r = t >> 3, q = (t & 7) * 4;
    float4 xv = *reinterpret_cast<const float4*>(x + (c0 + r)*HWN + p0 + q);
    float sc = d_scale[c0 + r];
    float4 v; v.x = xv.x*sc; v.y = xv.y*sc; v.z = xv.z*sc; v.w = xv.w*sc;
    *reinterpret_cast<float4*>(d_out32 + (c0 + r)*HWN + p0 + q) = v;
    V[r][q+0] = v.x; V[r][q+1] = v.y; V[r][q+2] = v.z; V[r][q+3] = v.w;
    S[r][q+0] = 1.f/(1.f+expf(-v.x));
    S[r][q+1] = 1.f/(1.f+expf(-v.y));
    S[r][q+2] = 1.f/(1.f+expf(-v.z));
    S[r][q+3] = 1.f/(1.f+expf(-v.w));
    __syncthreads();
    int pr = t >> 3, cq = (t & 7) * 4;
    float4 ov, sv;
    ov.x = V[cq+0][pr]; ov.y = V[cq+1][pr]; ov.z = V[cq+2][pr]; ov.w = V[cq+3][pr];
    sv.x = S[cq+0][pr]; sv.y = S[cq+1][pr]; sv.z = S[cq+2][pr]; sv.w = S[cq+3][pr];
    *reinterpret_cast<float4*>(d_out32T + (p0 + pr)*512 + c0 + cq) = ov;
    *reinterpret_cast<float4*>(d_sigT   + (p0 + pr)*512 + c0 + cq) = sv;
}

// ---- gaussian stage 1 ----
__global__ void k_gauss1() {
    int c = blockIdx.x, t = threadIdx.x;
    __shared__ float sO[1024], sG[1024];
    #pragma unroll
    for (int j = 0; j < 4; j++) {
        sO[t + j*256] = d_out32[c*1024 + t + j*256];
        sG[t + j*256] = d_G[t + j*256];
    }
    __syncthreads();
    #pragma unroll
    for (int j = 0; j < 4; j++) {
        int e = t + j*256;
        int i = e >> 5, y = e & 31;
        float acc = 0.f;
        #pragma unroll
        for (int xx = 0; xx < 32; xx++) acc += sG[i*32 + xx] * sO[xx*32 + y];
        d_tmp[c*1024 + e] = acc;
    }
}

// ---- gaussian stage 2 ----
__global__ void k_gauss2() {
    int i = blockIdx.x;
    int c0 = blockIdx.y * 128;
    int t = threadIdx.x;
    __shared__ float sm[128][33];
    __shared__ float gk[1024];
    #pragma unroll
    for (int l = t; l < 1024; l += 256) gk[l] = d_G[l];
    #pragma unroll
    for (int it = 0; it < 4; it++) {
        int s = t + it*256;
        int cc = s >> 3, yq = (s & 7) * 4;
        float4 v = *reinterpret_cast<const float4*>(d_tmp + (c0+cc)*1024 + i*32 + yq);
        sm[cc][yq+0] = v.x; sm[cc][yq+1] = v.y; sm[cc][yq+2] = v.z; sm[cc][yq+3] = v.w;
    }
    __syncthreads();
    int c = t & 127, kb = t >> 7;
    #pragma unroll
    for (int j = 0; j < 16; j++) {
        int k = kb + j*2;
        float acc = 0.f;
        #pragma unroll
        for (int y = 0; y < 32; y++) acc += gk[k*32 + y] * sm[c][y];
        d_cat[(i*32 + k)*512 + c0 + c] = acc;
    }
}

// ---- fused CSA ----
__global__ void k_csa() {
    int p = blockIdx.x;
    int h = p >> 5, w = p & 31;
    int t = threadIdx.x;
    __shared__ float wred[4][9];
    __shared__ float sA[9];
    int pn[9]; bool val[9];
    #pragma unroll
    for (int di = 0; di < 3; di++)
        #pragma unroll
        for (int dj = 0; dj < 3; dj++) {
            int d = di*3 + dj;
            int gh = h + di - 1, gw = w + dj - 1;
            val[d] = (gh >= 0) & (gh < 32) & (gw >= 0) & (gw < 32);
            pn[d] = (gh*32 + gw) * 512;
        }
    float4 cen = *reinterpret_cast<const float4*>(d_sigT + p*512 + t*4);
    float part[9];
    #pragma unroll
    for (int d = 0; d < 9; d++) {
        float pd = 0.f;
        if (val[d]) {
            float4 nb = *reinterpret_cast<const float4*>(d_sigT + pn[d] + t*4);
            pd = cen.x*nb.x + cen.y*nb.y + cen.z*nb.z + cen.w*nb.w;
        }
        part[d] = pd;
    }
    int lane = t & 31, wid = t >> 5;
    #pragma unroll
    for (int d = 0; d < 9; d++) {
        float v = part[d];
        #pragma unroll
        for (int o = 16; o > 0; o >>= 1) v += __shfl_xor_sync(~0u, v, o);
        if (lane == 0) wred[wid][d] = v;
    }
    __syncthreads();
    if (t == 0) {
        float sc[9];
        #pragma unroll
        for (int d = 0; d < 9; d++)
            sc[d] = (wred[0][d] + wred[1][d] + wred[2][d] + wred[3][d]) * (1.f/512.f);
        float m = sc[0];
        #pragma unroll
        for (int d = 1; d < 9; d++) m = fmaxf(m, sc[d]);
        float e[9], ss = 0.f;
        #pragma unroll
        for (int d = 0; d < 9; d++) { e[d] = expf(sc[d] - m); ss += e[d]; }
        float inv = 1.f / ss;
        #pragma unroll
        for (int d = 0; d < 9; d++) sA[d] = e[d] * inv;
    }
    __syncthreads();
    float4 acc = make_float4(0.f, 0.f, 0.f, 0.f);
    #pragma unroll
    for (int d = 0; d < 9; d++) {
        if (val[d]) {
            float a = sA[d];
            float4 nb = *reinterpret_cast<const float4*>(d_out32T + pn[d] + t*4);
            acc.x += a*nb.x; acc.y += a*nb.y; acc.z += a*nb.z; acc.w += a*nb.w;
        }
    }
    *reinterpret_cast<float4*>(d_cat + CHW + p*512 + t*4) = acc;
}

// ==================== mma.sync bf16-split GEMM (generic PTX, no tcgen05) ====
// d_y[z][m,n] = sum_{k in z-range} Wd[m,k]*d_cat[k*1024+n]; fp32 via bf16 hi/lo.
// CTA tile 128x128, k-split 4 (256 k each), k-chunks of 32 in smem.
// smem byte layout: Ah[128][40b16] @0 (10240), Al @10240, Bh[32][136b16] @20480 (8704), Bl @29184.
#define SMA_PITCH 80     // bytes per A row (40 b16)
#define SMB_PITCH 272    // bytes per B row (136 b16)
#define OFF_AL 10240
#define OFF_BH 20480
#define OFF_BL 29184

#define LDM_X4(r0,r1,r2,r3,addr) \
  asm volatile("ldmatrix.sync.aligned.m8n8.x4.shared.b16 {%0,%1,%2,%3},[%4];" \
    : "=r"(r0),"=r"(r1),"=r"(r2),"=r"(r3) : "r"(addr))
#define LDM_X4T(r0,r1,r2,r3,addr) \
  asm volatile("ldmatrix.sync.aligned.m8n8.x4.trans.shared.b16 {%0,%1,%2,%3},[%4];" \
    : "=r"(r0),"=r"(r1),"=r"(r2),"=r"(r3) : "r"(addr))
#define MMA(d,a,b0,b1) \
  asm volatile("mma.sync.aligned.m16n8k16.row.col.f32.bf16.bf16.f32 " \
    "{%0,%1,%2,%3},{%4,%5,%6,%7},{%8,%9},{%0,%1,%2,%3};" \
    : "+f"(d[0]),"+f"(d[1]),"+f"(d[2]),"+f"(d[3]) \
    : "r"(a[0]),"r"(a[1]),"r"(a[2]),"r"(a[3]),"r"(b0),"r"(b1))

__device__ __forceinline__ uint32_t smem_u32(const void* p) {
    uint32_t a;
    asm("{ .reg .u64 t; cvta.to.shared.u64 t, %1; cvt.u32.u64 %0, t; }" : "=r"(a) : "l"(p));
    return a;
}
__device__ __forceinline__ uint32_t pack_bf2(float a, float b) {
    __nv_bfloat162 t(__float2bfloat16_rn(a), __float2bfloat16_rn(b));
    return *reinterpret_cast<uint32_t*>(&t);
}
__device__ __forceinline__ void split4(const float4& v, uint2& hi, uint2& lo) {
    float h0 = __bfloat162float(__float2bfloat16_rn(v.x));
    float h1 = __bfloat162float(__float2bfloat16_rn(v.y));
    float h2 = __bfloat162float(__float2bfloat16_rn(v.z));
    float h3 = __bfloat162float(__float2bfloat16_rn(v.w));
    hi = make_uint2(pack_bf2(h0, h1), pack_bf2(h2, h3));
    lo = make_uint2(pack_bf2(v.x - h0, v.y - h1), pack_bf2(v.z - h2, v.w - h3));
}

__global__ void __launch_bounds__(256) k_gemm_mma(const float* __restrict__ Wd) {
    __shared__ __align__(16) char sm[37888];
    uint32_t sb = smem_u32(sm);
    int t = threadIdx.x, wid = t >> 5, lane = t & 31;
    int n0 = blockIdx.x * 128;
    int m0 = blockIdx.y * 128;
    int kz = blockIdx.z * 256;
    int wm = (wid & 1) * 64, wn = (wid >> 1) * 32;

    float acc[4][4][4];
    #pragma unroll
    for (int a = 0; a < 4; a++)
        #pragma unroll
        for (int b = 0; b < 4; b++)
            #pragma unroll
            for (int cxx = 0; cxx < 4; cxx++) acc[a][b][cxx] = 0.f;

    int q = lane >> 3, r = lane & 7;
    uint32_t a_lm = sb + (uint32_t)(wm + r + ((q & 1) << 3)) * SMA_PITCH + ((q >> 1) << 3) * 2;
    uint32_t b_lm = sb + OFF_BH + (uint32_t)(r + ((q & 1) << 3)) * SMB_PITCH
                  + (uint32_t)(wn + ((q >> 1) << 3)) * 2;

    int am = t >> 3,  akq = (t & 7) * 4;    // A: [m 0..127][k quad]
    int bk = t >> 5,  bnq = (t & 31) * 4;   // B: [k 0..31][n quad]
    const float* ag = Wd + (size_t)(m0 + am)*1024 + kz + akq;
    const float* bg = d_cat + (size_t)(kz + bk)*1024 + n0 + bnq;
    char* sma = sm + am*SMA_PITCH + akq*2;
    char* smb = sm + OFF_BH + bk*SMB_PITCH + bnq*2;

    for (int kc = 0; kc < 8; kc++) {
        float4 av[4], bv[4];
        #pragma unroll
        for (int it = 0; it < 4; it++) {
            av[it] = *reinterpret_cast<const float4*>(ag + kc*32 + it*32*1024);
            bv[it] = *reinterpret_cast<const float4*>(bg + (size_t)kc*32*1024 + it*8*1024);
        }
        __syncthreads();
        #pragma unroll
        for (int it = 0; it < 4; it++) {
            uint2 hi, lo;
            split4(av[it], hi, lo);
            *reinterpret_cast<uint2*>(sma + it*32*SMA_PITCH) = hi;
            *reinterpret_cast<uint2*>(sma + it*32*SMA_PITCH + OFF_AL) = lo;
            split4(bv[it], hi, lo);
            *reinterpret_cast<uint2*>(smb + it*8*SMB_PITCH) = hi;
            *reinterpret_cast<uint2*>(smb + it*8*SMB_PITCH + (OFF_BL - OFF_BH)) = lo;
        }
        __syncthreads();
        #pragma unroll
        for (int ks = 0; ks < 2; ks++) {
            uint32_t ah[4][4], al[4][4], bh[2][4], bl[2][4];
            #pragma unroll
            for (int mi = 0; mi < 4; mi++) {
                uint32_t ad = a_lm + mi*16*SMA_PITCH + ks*32;
                LDM_X4(ah[mi][0], ah[mi][1], ah[mi][2], ah[mi][3], ad);
                LDM_X4(al[mi][0], al[mi][1], al[mi][2], al[mi][3], ad + OFF_AL);
            }
            #pragma unroll
            for (int nj = 0; nj < 2; nj++) {
                uint32_t bd = b_lm + nj*32 + ks*16*SMB_PITCH;
                LDM_X4T(bh[nj][0], bh[nj][1], bh[nj][2], bh[nj][3], bd);
                LDM_X4T(bl[nj][0], bl[nj][1], bl[nj][2], bl[nj][3], bd + (OFF_BL - OFF_BH));
            }
            #pragma unroll
            for (int mi = 0; mi < 4; mi++) {
                #pragma unroll
                for (int nj = 0; nj < 2; nj++) {
                    MMA(acc[mi][2*nj],   ah[mi], bh[nj][0], bh[nj][1]);
                    MMA(acc[mi][2*nj],   ah[mi], bl[nj][0], bl[nj][1]);
                    MMA(acc[mi][2*nj],   al[mi], bh[nj][0], bh[nj][1]);
                    MMA(acc[mi][2*nj+1], ah[mi], bh[nj][2], bh[nj][3]);
                    MMA(acc[mi][2*nj+1], ah[mi], bl[nj][2], bl[nj][3]);
                    MMA(acc[mi][2*nj+1], al[mi], bh[nj][2], bh[nj][3]);
                }
            }
        }
    }
    int g = lane >> 2, tq = lane & 3;
    float* base = d_y + (size_t)blockIdx.z * CHW;
    #pragma unroll
    for (int mi = 0; mi < 4; mi++) {
        int row = m0 + wm + mi*16 + g;
        #pragma unroll
        for (int ni = 0; ni < 4; ni++) {
            int col = n0 + wn + ni*8 + tq*2;
            *reinterpret_cast<float2*>(base + (size_t)row*1024 + col) =
                make_float2(acc[mi][ni][0], acc[mi][ni][1]);
            *reinterpret_cast<float2*>(base + (size_t)(row+8)*1024 + col) =
                make_float2(acc[mi][ni][2], acc[mi][ni][3]);
        }
    }
}

// ---- instance norm (+ k-split reduce) + leaky relu(0.2) ----
__global__ void k_inorm(float* __restrict__ out) {
    int o = blockIdx.x, t = threadIdx.x;
    __shared__ float red[8];
    __shared__ float bmu, brs;
    float4 v0 = reinterpret_cast<const float4*>(d_y + 0*CHW + o*1024)[t];
    float4 v1 = reinterpret_cast<const float4*>(d_y + 1*CHW + o*1024)[t];
    float4 v2 = reinterpret_cast<const float4*>(d_y + 2*CHW + o*1024)[t];
    float4 v3 = reinterpret_cast<const float4*>(d_y + 3*CHW + o*1024)[t];
    float4 v;
    v.x = (v0.x + v1.x) + (v2.x + v3.x);
    v.y = (v0.y + v1.y) + (v2.y + v3.y);
    v.z = (v0.z + v1.z) + (v2.z + v3.z);
    v.w = (v0.w + v1.w) + (v2.w + v3.w);
    float s = v.x + v.y + v.z + v.w;
    #pragma unroll
    for (int off = 16; off > 0; off >>= 1) s += __shfl_xor_sync(~0u, s, off);
    if ((t & 31) == 0) red[t >> 5] = s;
    __syncthreads();
    if (t == 0) {
        float tot = 0.f;
        #pragma unroll
        for (int w = 0; w < 8; w++) tot += red[w];
        bmu = tot * (1.f/1024.f);
    }
    __syncthreads();
    float mu = bmu;
    float dx = v.x - mu, dy = v.y - mu, dz = v.z - mu, dw = v.w - mu;
    float qq = dx*dx + dy*dy + dz*dz + dw*dw;
    #pragma unroll
    for (int off = 16; off > 0; off >>= 1) qq += __shfl_xor_sync(~0u, qq, off);
    if ((t & 31) == 0) red[t >> 5] = qq;
    __syncthreads();
    if (t == 0) {
        float tot = 0.f;
        #pragma unroll
        for (int w = 0; w < 8; w++) tot += red[w];
        brs = rsqrtf(tot * (1.f/1024.f) + 1e-5f);
    }
    __syncthreads();
    float rs = brs;
    float4 rr;
    rr.x = dx*rs; rr.y = dy*rs; rr.z = dz*rs; rr.w = dw*rs;
    rr.x = rr.x >= 0.f ? rr.x : 0.2f*rr.x;
    rr.y = rr.y >= 0.f ? rr.y : 0.2f*rr.y;
    rr.z = rr.z >= 0.f ? rr.z : 0.2f*rr.z;
    rr.w = rr.w >= 0.f ? rr.w : 0.2f*rr.w;
    reinterpret_cast<float4*>(out + o*1024)[t] = rr;
}

extern "C" void kernel_launch(void* const* d_in, const int* in_sizes, int n_in,
                              void* d_out, int out_size) {
    const float* x  = (const float*)d_in[0];
    const float* w1 = (const float*)d_in[1];
    const float* w2 = (const float*)d_in[2];
    const float* wd = (const float*)d_in[3];
    float* out = (float*)d_out;

    k_gauss<<<1, 32>>>();
    k_mean<<<512, 256>>>(x);
    k_se<<<1, 512>>>(w1, w2);
    k_trans<<<dim3(32, 16), 256>>>(x);
    k_gauss1<<<512, 256>>>();
    k_gauss2<<<dim3(32, 4), 256>>>();
    k_csa<<<1024, 128>>>();
    k_gemm_mma<<<dim3(8, 4, 4), 256>>>(wd);
    k_inorm<<<512, 256>>>(out);
}

// round 7
// speedup vs baseline: 2.5463x; 1.1088x over previous
#include <cuda_runtime.h>
#include <cuda_bf16.h>
#include <math.h>
#include <stdint.h>

#define C 512
#define HWN 1024
#define CHW (C*HWN)

__device__ __align__(16) float d_G[1024];        // G[i*32+x]
__device__ float d_mean[C];
__device__ float d_scale[C];
__device__ __align__(16) float d_out32T[CHW];    // [hw][c]
__device__ __align__(16) float d_sigT[CHW];      // [hw][c]
__device__ __align__(16) float d_tmpT[CHW];      // [(i*32+y)][c]
__device__ __align__(16) float d_cat[2*CHW];     // gus flat (p*512+c) ; csa flat
__device__ __align__(16) float d_y[4*CHW];       // 4 k-split partials

__device__ __forceinline__ float tanhapx(float x) {
    float y; asm("tanh.approx.f32 %0, %1;" : "=f"(y) : "f"(x)); return y;
}
__device__ __forceinline__ float sig1(float v) {   // sigmoid via 1 MUFU
    return fmaf(tanhapx(0.5f * v), 0.5f, 0.5f);
}

// ---- blocks 0..511: channel means; block 512: gaussian weights ----
__global__ void k_init(const float* __restrict__ x) {
    if (blockIdx.x == 512) {
        int i = threadIdx.x;
        if (i < 32) {
            float ev[32]; float s = 0.f;
            #pragma unroll
            for (int xx = 0; xx < 32; xx++) {
                float dd = (float)(xx - i);
                float e = expf(-dd * dd * (1.0f/4.5f));
                ev[xx] = e; s += e;
            }
            float inv = 1.f / s;
            #pragma unroll
            for (int xx = 0; xx < 32; xx++) d_G[i*32 + xx] = ev[xx] * inv;
        }
        return;
    }
    int c = blockIdx.x, t = threadIdx.x;
    float4 v = reinterpret_cast<const float4*>(x + c*HWN)[t];
    float s = v.x + v.y + v.z + v.w;
    #pragma unroll
    for (int o = 16; o > 0; o >>= 1) s += __shfl_xor_sync(~0u, s, o);
    __shared__ float red[8];
    if ((t & 31) == 0) red[t >> 5] = s;
    __syncthreads();
    if (t == 0) {
        float tot = 0.f;
        #pragma unroll
        for (int w = 0; w < 8; w++) tot += red[w];
        d_mean[c] = tot * (1.f/1024.f);
    }
}

// ---- SE (exact expf; only 544 of them) ----
__global__ void k_se(const float* __restrict__ w1, const float* __restrict__ w2) {
    __shared__ float s[512], s1[32];
    int t = threadIdx.x;
    s[t] = d_mean[t];
    __syncthreads();
    int o = t >> 4, l = t & 15;
    float a = 0.f;
    #pragma unroll
    for (int j = 0; j < 8; j++) {
        int c = (l + j*16) * 4;
        float4 w = *reinterpret_cast<const float4*>(w1 + o*512 + c);
        a += w.x*s[c] + w.y*s[c+1] + w.z*s[c+2] + w.w*s[c+3];
    }
    #pragma unroll
    for (int off = 8; off > 0; off >>= 1) a += __shfl_down_sync(~0u, a, off, 16);
    if (l == 0) s1[o] = fmaxf(a, 0.f);
    __syncthreads();
    float b = 0.f;
    const float4* w2p = reinterpret_cast<const float4*>(w2 + t*32);
    #pragma unroll
    for (int j = 0; j < 8; j++) {
        float4 w = w2p[j];
        b += w.x*s1[j*4+0] + w.y*s1[j*4+1] + w.z*s1[j*4+2] + w.w*s1[j*4+3];
    }
    d_scale[t] = 1.f / (1.f + expf(-b));
}

// ---- scale + sigmoid(tanh.approx) + transpose -> out32T, sigT ----
__global__ void k_trans(const float* __restrict__ x) {
    int p0 = blockIdx.x * 32;
    int c0 = blockIdx.y * 32;
    int t = threadIdx.x;
    __shared__ float V[32][33], S[32][33];
    int r = t >> 3, q = (t & 7) * 4;
    float4 xv = *reinterpret_cast<const float4*>(x + (c0 + r)*HWN + p0 + q);
    float sc = d_scale[c0 + r];
    float4 v; v.x = xv.x*sc; v.y = xv.y*sc; v.z = xv.z*sc; v.w = xv.w*sc;
    V[r][q+0] = v.x; V[r][q+1] = v.y; V[r][q+2] = v.z; V[r][q+3] = v.w;
    S[r][q+0] = sig1(v.x);
    S[r][q+1] = sig1(v.y);
    S[r][q+2] = sig1(v.z);
    S[r][q+3] = sig1(v.w);
    __syncthreads();
    int pr = t >> 3, cq = (t & 7) * 4;
    float4 ov, sv;
    ov.x = V[cq+0][pr]; ov.y = V[cq+1][pr]; ov.z = V[cq+2][pr]; ov.w = V[cq+3][pr];
    sv.x = S[cq+0][pr]; sv.y = S[cq+1][pr]; sv.z = S[cq+2][pr]; sv.w = S[cq+3][pr];
    *reinterpret_cast<float4*>(d_out32T + (p0 + pr)*512 + c0 + cq) = ov;
    *reinterpret_cast<float4*>(d_sigT   + (p0 + pr)*512 + c0 + cq) = sv;
}

// ---- fused: blocks 0..127 = gaussian stage (phase 0: stage1, phase 1: stage2);
//      blocks 128..383 = CSA, 2 pixels each (phase selects pixel half) ----
__global__ void k_par(int phase) {
    __shared__ float sm[4096];       // [32 rows][128 c]
    __shared__ float sG[1024];
    __shared__ float cred[2][4][9];
    __shared__ float cA[2][9];
    int t = threadIdx.x;
    int bid = blockIdx.x;
    if (bid < 128) {
        #pragma unroll
        for (int j = 0; j < 4; j++) sG[t + j*256] = d_G[t + j*256];
        int c0 = (bid & 3) * 128;
        int rs = bid >> 2;   // y (phase 0) or i (phase 1)
        #pragma unroll
        for (int j = 0; j < 4; j++) {
            int idx = t + j*256;
            int rr = idx >> 5, cq = (idx & 31) * 4;
            const float* src = (phase == 0)
                ? d_out32T + (size_t)(rr*32 + rs)*512 + c0 + cq
                : d_tmpT   + (size_t)(rs*32 + rr)*512 + c0 + cq;
            *reinterpret_cast<float4*>(&sm[rr*128 + cq]) =
                *reinterpret_cast<const float4*>(src);
        }
        __syncthreads();
        int cg = t >> 5;           // 8 groups of 4 output rows
        int c4 = (t & 31) * 4;
        float4 acc[4];
        #pragma unroll
        for (int u = 0; u < 4; u++) acc[u] = make_float4(0.f, 0.f, 0.f, 0.f);
        #pragma unroll
        for (int x = 0; x < 32; x += 4) {
            float4 sv0 = *reinterpret_cast<const float4*>(&sm[(x+0)*128 + c4]);
            float4 sv1 = *reinterpret_cast<const float4*>(&sm[(x+1)*128 + c4]);
            float4 sv2 = *reinterpret_cast<const float4*>(&sm[(x+2)*128 + c4]);
            float4 sv3 = *reinterpret_cast<const float4*>(&sm[(x+3)*128 + c4]);
            #pragma unroll
            for (int ii = 0; ii < 4; ii++) {
                int i = cg*4 + ii;
                float4 g = *reinterpret_cast<const float4*>(&sG[i*32 + x]);
                acc[ii].x += g.x*sv0.x + g.y*sv1.x + g.z*sv2.x + g.w*sv3.x;
                acc[ii].y += g.x*sv0.y + g.y*sv1.y + g.z*sv2.y + g.w*sv3.y;
                acc[ii].z += g.x*sv0.z + g.y*sv1.z + g.z*sv2.z + g.w*sv3.z;
                acc[ii].w += g.x*sv0.w + g.y*sv1.w + g.z*sv2.w + g.w*sv3.w;
            }
        }
        #pragma unroll
        for (int ii = 0; ii < 4; ii++) {
            int i = cg*4 + ii;
            size_t row = (phase == 0) ? (size_t)(i*32 + rs) : (size_t)(rs*32 + i);
            float* dst = (phase == 0) ? d_tmpT : d_cat;
            *reinterpret_cast<float4*>(dst + row*512 + c0 + c4) = acc[ii];
        }
    } else {
        int half = t >> 7, wt = t & 127;
        int p = phase*512 + (bid - 128)*2 + half;
        int h = p >> 5, w = p & 31;
        int pn[9]; bool val[9];
        #pragma unroll
        for (int di = 0; di < 3; di++)
            #pragma unroll
            for (int dj = 0; dj < 3; dj++) {
                int d = di*3 + dj;
                int gh = h + di - 1, gw = w + dj - 1;
                val[d] = (gh >= 0) & (gh < 32) & (gw >= 0) & (gw < 32);
                pn[d] = (gh*32 + gw) * 512;
            }
        float4 cen = *reinterpret_cast<const float4*>(d_sigT + p*512 + wt*4);
        float part[9];
        #pragma unroll
        for (int d = 0; d < 9; d++) {
            float pd = 0.f;
            if (val[d]) {
                float4 nb = *reinterpret_cast<const float4*>(d_sigT + pn[d] + wt*4);
                pd = cen.x*nb.x + cen.y*nb.y + cen.z*nb.z + cen.w*nb.w;
            }
            part[d] = pd;
        }
        int lane = wt & 31, wid = wt >> 5;
        #pragma unroll
        for (int d = 0; d < 9; d++) {
            float v = part[d];
            #pragma unroll
            for (int o = 16; o > 0; o >>= 1) v += __shfl_xor_sync(~0u, v, o);
            if (lane == 0) cred[half][wid][d] = v;
        }
        __syncthreads();
        if (wt == 0) {
            float sc[9];
            #pragma unroll
            for (int d = 0; d < 9; d++)
                sc[d] = (cred[half][0][d] + cred[half][1][d]
                       + cred[half][2][d] + cred[half][3][d]) * (1.f/512.f);
            float m = sc[0];
            #pragma unroll
            for (int d = 1; d < 9; d++) m = fmaxf(m, sc[d]);
            float e[9], ss = 0.f;
            #pragma unroll
            for (int d = 0; d < 9; d++) { e[d] = expf(sc[d] - m); ss += e[d]; }
            float inv = 1.f / ss;
            #pragma unroll
            for (int d = 0; d < 9; d++) cA[half][d] = e[d] * inv;
        }
        __syncthreads();
        float4 acc = make_float4(0.f, 0.f, 0.f, 0.f);
        #pragma unroll
        for (int d = 0; d < 9; d++) {
            if (val[d]) {
                float a = cA[half][d];
                float4 nb = *reinterpret_cast<const float4*>(d_out32T + pn[d] + wt*4);
                acc.x += a*nb.x; acc.y += a*nb.y; acc.z += a*nb.z; acc.w += a*nb.w;
            }
        }
        *reinterpret_cast<float4*>(d_cat + CHW + p*512 + wt*4) = acc;
    }
}

// ==================== mma.sync bf16-split GEMM ====================
#define SMA_PITCH 80
#define SMB_PITCH 272
#define OFF_AL 10240
#define OFF_BH 20480
#define OFF_BL 29184

#define LDM_X4(r0,r1,r2,r3,addr) \
  asm volatile("ldmatrix.sync.aligned.m8n8.x4.shared.b16 {%0,%1,%2,%3},[%4];" \
    : "=r"(r0),"=r"(r1),"=r"(r2),"=r"(r3) : "r"(addr))
#define LDM_X4T(r0,r1,r2,r3,addr) \
  asm volatile("ldmatrix.sync.aligned.m8n8.x4.trans.shared.b16 {%0,%1,%2,%3},[%4];" \
    : "=r"(r0),"=r"(r1),"=r"(r2),"=r"(r3) : "r"(addr))
#define MMA(d,a,b0,b1) \
  asm volatile("mma.sync.aligned.m16n8k16.row.col.f32.bf16.bf16.f32 " \
    "{%0,%1,%2,%3},{%4,%5,%6,%7},{%8,%9},{%0,%1,%2,%3};" \
    : "+f"(d[0]),"+f"(d[1]),"+f"(d[2]),"+f"(d[3]) \
    : "r"(a[0]),"r"(a[1]),"r"(a[2]),"r"(a[3]),"r"(b0),"r"(b1))

__device__ __forceinline__ uint32_t smem_u32(const void* p) {
    uint32_t a;
    asm("{ .reg .u64 t; cvta.to.shared.u64 t, %1; cvt.u32.u64 %0, t; }" : "=r"(a) : "l"(p));
    return a;
}
__device__ __forceinline__ uint32_t pack_bf2(float a, float b) {
    __nv_bfloat162 t(__float2bfloat16_rn(a), __float2bfloat16_rn(b));
    return *reinterpret_cast<uint32_t*>(&t);
}
__device__ __forceinline__ void split4(const float4& v, uint2& hi, uint2& lo) {
    float h0 = __bfloat162float(__float2bfloat16_rn(v.x));
    float h1 = __bfloat162float(__float2bfloat16_rn(v.y));
    float h2 = __bfloat162float(__float2bfloat16_rn(v.z));
    float h3 = __bfloat162float(__float2bfloat16_rn(v.w));
    hi = make_uint2(pack_bf2(h0, h1), pack_bf2(h2, h3));
    lo = make_uint2(pack_bf2(v.x - h0, v.y - h1), pack_bf2(v.z - h2, v.w - h3));
}

__global__ void __launch_bounds__(256) k_gemm_mma(const float* __restrict__ Wd) {
    __shared__ __align__(16) char sm[37888];
    uint32_t sb = smem_u32(sm);
    int t = threadIdx.x, wid = t >> 5, lane = t & 31;
    int n0 = blockIdx.x * 128;
    int m0 = blockIdx.y * 128;
    int kz = blockIdx.z * 256;
    int wm = (wid & 1) * 64, wn = (wid >> 1) * 32;

    float acc[4][4][4];
    #pragma unroll
    for (int a = 0; a < 4; a++)
        #pragma unroll
        for (int b = 0; b < 4; b++)
            #pragma unroll
            for (int cxx = 0; cxx < 4; cxx++) acc[a][b][cxx] = 0.f;

    int q = lane >> 3, r = lane & 7;
    uint32_t a_lm = sb + (uint32_t)(wm + r + ((q & 1) << 3)) * SMA_PITCH + ((q >> 1) << 3) * 2;
    uint32_t b_lm = sb + OFF_BH + (uint32_t)(r + ((q & 1) << 3)) * SMB_PITCH
                  + (uint32_t)(wn + ((q >> 1) << 3)) * 2;

    int am = t >> 3,  akq = (t & 7) * 4;
    int bk = t >> 5,  bnq = (t & 31) * 4;
    const float* ag = Wd + (size_t)(m0 + am)*1024 + kz + akq;
    const float* bg = d_cat + (size_t)(kz + bk)*1024 + n0 + bnq;
    char* sma = sm + am*SMA_PITCH + akq*2;
    char* smb = sm + OFF_BH + bk*SMB_PITCH + bnq*2;

    for (int kc = 0; kc < 8; kc++) {
        float4 av[4], bv[4];
        #pragma unroll
        for (int it = 0; it < 4; it++) {
            av[it] = *reinterpret_cast<const float4*>(ag + kc*32 + it*32*1024);
            bv[it] = *reinterpret_cast<const float4*>(bg + (size_t)kc*32*1024 + it*8*1024);
        }
        __syncthreads();
        #pragma unroll
        for (int it = 0; it < 4; it++) {
            uint2 hi, lo;
            split4(av[it], hi, lo);
            *reinterpret_cast<uint2*>(sma + it*32*SMA_PITCH) = hi;
            *reinterpret_cast<uint2*>(sma + it*32*SMA_PITCH + OFF_AL) = lo;
            split4(bv[it], hi, lo);
            *reinterpret_cast<uint2*>(smb + it*8*SMB_PITCH) = hi;
            *reinterpret_cast<uint2*>(smb + it*8*SMB_PITCH + (OFF_BL - OFF_BH)) = lo;
        }
        __syncthreads();
        #pragma unroll
        for (int ks = 0; ks < 2; ks++) {
            uint32_t ah[4][4], al[4][4], bh[2][4], bl[2][4];
            #pragma unroll
            for (int mi = 0; mi < 4; mi++) {
                uint32_t ad = a_lm + mi*16*SMA_PITCH + ks*32;
                LDM_X4(ah[mi][0], ah[mi][1], ah[mi][2], ah[mi][3], ad);
                LDM_X4(al[mi][0], al[mi][1], al[mi][2], al[mi][3], ad + OFF_AL);
            }
            #pragma unroll
            for (int nj = 0; nj < 2; nj++) {
                uint32_t bd = b_lm + nj*32 + ks*16*SMB_PITCH;
                LDM_X4T(bh[nj][0], bh[nj][1], bh[nj][2], bh[nj][3], bd);
                LDM_X4T(bl[nj][0], bl[nj][1], bl[nj][2], bl[nj][3], bd + (OFF_BL - OFF_BH));
            }
            #pragma unroll
            for (int mi = 0; mi < 4; mi++) {
                #pragma unroll
                for (int nj = 0; nj < 2; nj++) {
                    MMA(acc[mi][2*nj],   ah[mi], bh[nj][0], bh[nj][1]);
                    MMA(acc[mi][2*nj],   ah[mi], bl[nj][0], bl[nj][1]);
                    MMA(acc[mi][2*nj],   al[mi], bh[nj][0], bh[nj][1]);
                    MMA(acc[mi][2*nj+1], ah[mi], bh[nj][2], bh[nj][3]);
                    MMA(acc[mi][2*nj+1], ah[mi], bl[nj][2], bl[nj][3]);
                    MMA(acc[mi][2*nj+1], al[mi], bh[nj][2], bh[nj][3]);
                }
            }
        }
    }
    int g = lane >> 2, tq = lane & 3;
    float* base = d_y + (size_t)blockIdx.z * CHW;
    #pragma unroll
    for (int mi = 0; mi < 4; mi++) {
        int row = m0 + wm + mi*16 + g;
        #pragma unroll
        for (int ni = 0; ni < 4; ni++) {
            int col = n0 + wn + ni*8 + tq*2;
            *reinterpret_cast<float2*>(base + (size_t)row*1024 + col) =
                make_float2(acc[mi][ni][0], acc[mi][ni][1]);
            *reinterpret_cast<float2*>(base + (size_t)(row+8)*1024 + col) =
                make_float2(acc[mi][ni][2], acc[mi][ni][3]);
        }
    }
}

// ---- instance norm (+ k-split reduce) + leaky relu(0.2) ----
__global__ void k_inorm(float* __restrict__ out) {
    int o = blockIdx.x, t = threadIdx.x;
    __shared__ float red[8];
    __shared__ float bmu, brs;
    float4 v0 = reinterpret_cast<const float4*>(d_y + 0*CHW + o*1024)[t];
    float4 v1 = reinterpret_cast<const float4*>(d_y + 1*CHW + o*1024)[t];
    float4 v2 = reinterpret_cast<const float4*>(d_y + 2*CHW + o*1024)[t];
    float4 v3 = reinterpret_cast<const float4*>(d_y + 3*CHW + o*1024)[t];
    float4 v;
    v.x = (v0.x + v1.x) + (v2.x + v3.x);
    v.y = (v0.y + v1.y) + (v2.y + v3.y);
    v.z = (v0.z + v1.z) + (v2.z + v3.z);
    v.w = (v0.w + v1.w) + (v2.w + v3.w);
    float s = v.x + v.y + v.z + v.w;
    #pragma unroll
    for (int off = 16; off > 0; off >>= 1) s += __shfl_xor_sync(~0u, s, off);
    if ((t & 31) == 0) red[t >> 5] = s;
    __syncthreads();
    if (t == 0) {
        float tot = 0.f;
        #pragma unroll
        for (int w = 0; w < 8; w++) tot += red[w];
        bmu = tot * (1.f/1024.f);
    }
    __syncthreads();
    float mu = bmu;
    float dx = v.x - mu, dy = v.y - mu, dz = v.z - mu, dw = v.w - mu;
    float qq = dx*dx + dy*dy + dz*dz + dw*dw;
    #pragma unroll
    for (int off = 16; off > 0; off >>= 1) qq += __shfl_xor_sync(~0u, qq, off);
    if ((t & 31) == 0) red[t >> 5] = qq;
    __syncthreads();
    if (t == 0) {
        float tot = 0.f;
        #pragma unroll
        for (int w = 0; w < 8; w++) tot += red[w];
        brs = rsqrtf(tot * (1.f/1024.f) + 1e-5f);
    }
    __syncthreads();
    float rs = brs;
    float4 rr;
    rr.x = dx*rs; rr.y = dy*rs; rr.z = dz*rs; rr.w = dw*rs;
    rr.x = rr.x >= 0.f ? rr.x : 0.2f*rr.x;
    rr.y = rr.y >= 0.f ? rr.y : 0.2f*rr.y;
    rr.z = rr.z >= 0.f ? rr.z : 0.2f*rr.z;
    rr.w = rr.w >= 0.f ? rr.w : 0.2f*rr.w;
    reinterpret_cast<float4*>(out + o*1024)[t] = rr;
}

extern "C" void kernel_launch(void* const* d_in, const int* in_sizes, int n_in,
                              void* d_out, int out_size) {
    const float* x  = (const float*)d_in[0];
    const float* w1 = (const float*)d_in[1];
    const float* w2 = (const float*)d_in[2];
    const float* wd = (const float*)d_in[3];
    float* out = (float*)d_out;

    k_init<<<513, 256>>>(x);
    k_se<<<1, 512>>>(w1, w2);
    k_trans<<<dim3(32, 16), 256>>>(x);
    k_par<<<384, 256>>>(0);
    k_par<<<384, 256>>>(1);
    k_gemm_mma<<<dim3(8, 4, 4), 256>>>(wd);
    k_inorm<<<512, 256>>>(out);
}